// round 7
// baseline (speedup 1.0000x reference)
#include <cuda_runtime.h>
#include <math_constants.h>

// Problem constants (fixed by the reference):
//   outputs: (B, C) fp32, targets: (B,) i32, ages: (B,) i32, weight: (C,) fp32
//   T = 2.0 softmax temperature; output = scalar fp32 mean loss.
//
// Evidence base (R1-R6): float4 two-pass (max then exp) row processing at
// 256 thr / 8 rows-per-block is the fastest stage-1 measured (~22.8us,
// 5.6 TB/s). Fusing the final reduce is worth ~4.2us of launch overhead,
// but __threadfence() (gpu-scope -> CCTL.IVALL L1 flush per block) cost
// ~6us in R3-R5. This round: fence-free fusion via acq_rel atomics.
#define B_ROWS 32768
#define C_COLS 1024
#define ROWS_PER_BLOCK 8
#define THREADS (ROWS_PER_BLOCK * 32)
#define NBLOCKS (B_ROWS / ROWS_PER_BLOCK) // 4096

// Scratch for deterministic single-launch reduction (no cudaMalloc allowed).
__device__ float g_partials[NBLOCKS];
__device__ unsigned int g_count = 0;

__global__ __launch_bounds__(THREADS)
void loss_fused_kernel(const float* __restrict__ outputs,
                       const int*   __restrict__ targets,
                       const int*   __restrict__ ages,
                       const float* __restrict__ weight,
                       float*       __restrict__ out) {
    const int warp = threadIdx.x >> 5;
    const int lane = threadIdx.x & 31;
    const int row  = blockIdx.x * ROWS_PER_BLOCK + warp;

    const float4* rp = reinterpret_cast<const float4*>(
        outputs + (size_t)row * C_COLS);

    // Load full row into registers, streaming hint (no reuse; 128MB >> L2).
    // All values live across the max pass -> ptxas front-batches the LDGs.
    float4 v[8];
#pragma unroll
    for (int k = 0; k < 8; ++k) v[k] = __ldcs(&rp[k * 32 + lane]);

    // Pass 1: scale by 1/T and per-lane max (4 parallel max chains).
    float m0 = -CUDART_INF_F, m1 = -CUDART_INF_F;
    float m2 = -CUDART_INF_F, m3 = -CUDART_INF_F;
#pragma unroll
    for (int k = 0; k < 8; ++k) {
        v[k].x *= 0.5f; v[k].y *= 0.5f; v[k].z *= 0.5f; v[k].w *= 0.5f;
        m0 = fmaxf(m0, v[k].x); m1 = fmaxf(m1, v[k].y);
        m2 = fmaxf(m2, v[k].z); m3 = fmaxf(m3, v[k].w);
    }
    float m = fmaxf(fmaxf(m0, m1), fmaxf(m2, m3));
#pragma unroll
    for (int off = 16; off > 0; off >>= 1)
        m = fmaxf(m, __shfl_xor_sync(0xFFFFFFFFu, m, off));

    // Pass 2: exp-sum with 4 parallel accumulators.
    float s0 = 0.0f, s1 = 0.0f, s2 = 0.0f, s3 = 0.0f;
#pragma unroll
    for (int k = 0; k < 8; ++k) {
        s0 += __expf(v[k].x - m);
        s1 += __expf(v[k].y - m);
        s2 += __expf(v[k].z - m);
        s3 += __expf(v[k].w - m);
    }
    float s = (s0 + s1) + (s2 + s3);
#pragma unroll
    for (int off = 16; off > 0; off >>= 1)
        s += __shfl_xor_sync(0xFFFFFFFFu, s, off);

    __shared__ float sh[ROWS_PER_BLOCK];
    if (lane == 0) {
        const float lse = m + __logf(s);
        const int   t    = targets[row];
        const float agef = (float)ages[row];
        const float delta = (agef > 50.0f && agef < 60.0f)
                                ? (agef - 50.0f) * 0.1f : 0.0f;
        // Re-reads of this row (L2 hit at worst: 2 loads/row, negligible).
        const float yt  = outputs[(size_t)row * C_COLS + t]     * 0.5f;
        const float yt1 = outputs[(size_t)row * C_COLS + t + 1] * 0.5f;
        const float loss = -((1.0f - delta) * weight[t]     * (yt  - lse)
                           +         delta  * weight[t + 1] * (yt1 - lse));
        sh[warp] = loss;
    }
    __syncthreads();

    // Fence-free completion protocol: release-increment the counter AFTER
    // writing our partial; the last block acquires on the same atomic, so
    // all partial writes are visible to it (PTX memory model), with NO
    // CCTL.IVALL L1 flush.
    __shared__ bool s_last;
    if (threadIdx.x == 0) {
        float p = 0.0f;
#pragma unroll
        for (int i = 0; i < ROWS_PER_BLOCK; ++i) p += sh[i];
        g_partials[blockIdx.x] = p;
        unsigned int prev;
        asm volatile("atom.add.acq_rel.gpu.u32 %0, [%1], 1;"
                     : "=r"(prev) : "l"(&g_count) : "memory");
        s_last = (prev == (unsigned int)(NBLOCKS - 1));
    }
    __syncthreads();

    if (!s_last) return;

    // Final reduce: this block reads all partials in a FIXED order
    // (deterministic output across replays). __ldcg (L2 path) avoids any
    // stale L1 lines for data written by other SMs.
    {
        const int tid = threadIdx.x;
        const float4* pp = reinterpret_cast<const float4*>(g_partials);
        float acc = 0.0f;
#pragma unroll
        for (int i = 0; i < NBLOCKS / (THREADS * 4); ++i) {
            const float4 w = __ldcg(&pp[tid + i * THREADS]);
            acc += (w.x + w.y) + (w.z + w.w);
        }
#pragma unroll
        for (int off = 16; off > 0; off >>= 1)
            acc += __shfl_xor_sync(0xFFFFFFFFu, acc, off);

        __shared__ float shw[ROWS_PER_BLOCK];
        if (lane == 0) shw[warp] = acc;
        __syncthreads();
        if (threadIdx.x == 0) {
            float total = 0.0f;
#pragma unroll
            for (int i = 0; i < ROWS_PER_BLOCK; ++i) total += shw[i];
            out[0] = total * (1.0f / (float)B_ROWS);
            g_count = 0; // reset for next graph replay (kernel boundary orders it)
        }
    }
}

extern "C" void kernel_launch(void* const* d_in, const int* in_sizes, int n_in,
                              void* d_out, int out_size) {
    const float* outputs = (const float*)d_in[0];
    const int*   targets = (const int*)d_in[1];
    const int*   ages    = (const int*)d_in[2];
    const float* weight  = (const float*)d_in[3];
    float*       out     = (float*)d_out;

    loss_fused_kernel<<<NBLOCKS, THREADS>>>(outputs, targets, ages, weight, out);
}

// round 8
// speedup vs baseline: 1.0099x; 1.0099x over previous
#include <cuda_runtime.h>
#include <math_constants.h>

// Problem constants (fixed by the reference):
//   outputs: (B, C) fp32, targets: (B,) i32, ages: (B,) i32, weight: (C,) fp32
//   T = 2.0 softmax temperature; output = scalar fp32 mean loss.
//
// R7 finding: every fused variant paid a per-block gpu-scope ACQUIRE
// (__threadfence, or the acquire half of atom.acq_rel) = L1-invalidate per
// block x 4096 blocks ~= the persistent ~5us gap vs the bare row kernel.
// Fix: producers use RELEASE-only (cheap store drain, no L1 flush); the
// single last block performs ONE acquire fence before reading partials.
#define B_ROWS 32768
#define C_COLS 1024
#define ROWS_PER_BLOCK 8
#define THREADS (ROWS_PER_BLOCK * 32)
#define NBLOCKS (B_ROWS / ROWS_PER_BLOCK) // 4096

// Scratch for deterministic single-launch reduction (no cudaMalloc allowed).
__device__ float g_partials[NBLOCKS];
__device__ unsigned int g_count = 0;

__global__ __launch_bounds__(THREADS)
void loss_fused_kernel(const float* __restrict__ outputs,
                       const int*   __restrict__ targets,
                       const int*   __restrict__ ages,
                       const float* __restrict__ weight,
                       float*       __restrict__ out) {
    const int warp = threadIdx.x >> 5;
    const int lane = threadIdx.x & 31;
    const int row  = blockIdx.x * ROWS_PER_BLOCK + warp;

    const float4* rp = reinterpret_cast<const float4*>(
        outputs + (size_t)row * C_COLS);

    // Load full row into registers, streaming hint (no reuse; 128MB >> L2).
    // All values live across the max pass -> ptxas front-batches the LDGs.
    float4 v[8];
#pragma unroll
    for (int k = 0; k < 8; ++k) v[k] = __ldcs(&rp[k * 32 + lane]);

    // Pass 1: scale by 1/T and per-lane max (4 parallel max chains).
    float m0 = -CUDART_INF_F, m1 = -CUDART_INF_F;
    float m2 = -CUDART_INF_F, m3 = -CUDART_INF_F;
#pragma unroll
    for (int k = 0; k < 8; ++k) {
        v[k].x *= 0.5f; v[k].y *= 0.5f; v[k].z *= 0.5f; v[k].w *= 0.5f;
        m0 = fmaxf(m0, v[k].x); m1 = fmaxf(m1, v[k].y);
        m2 = fmaxf(m2, v[k].z); m3 = fmaxf(m3, v[k].w);
    }
    float m = fmaxf(fmaxf(m0, m1), fmaxf(m2, m3));
#pragma unroll
    for (int off = 16; off > 0; off >>= 1)
        m = fmaxf(m, __shfl_xor_sync(0xFFFFFFFFu, m, off));

    // Pass 2: exp-sum with 4 parallel accumulators.
    float s0 = 0.0f, s1 = 0.0f, s2 = 0.0f, s3 = 0.0f;
#pragma unroll
    for (int k = 0; k < 8; ++k) {
        s0 += __expf(v[k].x - m);
        s1 += __expf(v[k].y - m);
        s2 += __expf(v[k].z - m);
        s3 += __expf(v[k].w - m);
    }
    float s = (s0 + s1) + (s2 + s3);
#pragma unroll
    for (int off = 16; off > 0; off >>= 1)
        s += __shfl_xor_sync(0xFFFFFFFFu, s, off);

    __shared__ float sh[ROWS_PER_BLOCK];
    if (lane == 0) {
        const float lse = m + __logf(s);
        const int   t    = targets[row];
        const float agef = (float)ages[row];
        const float delta = (agef > 50.0f && agef < 60.0f)
                                ? (agef - 50.0f) * 0.1f : 0.0f;
        const float yt  = outputs[(size_t)row * C_COLS + t]     * 0.5f;
        const float yt1 = outputs[(size_t)row * C_COLS + t + 1] * 0.5f;
        const float loss = -((1.0f - delta) * weight[t]     * (yt  - lse)
                           +         delta  * weight[t + 1] * (yt1 - lse));
        sh[warp] = loss;
    }
    __syncthreads();

    // Producer side: st.cg partial (to L2, past L1) + RELEASE-only atomic.
    // No L1 invalidate on this path.
    __shared__ bool s_last;
    if (threadIdx.x == 0) {
        float p = 0.0f;
#pragma unroll
        for (int i = 0; i < ROWS_PER_BLOCK; ++i) p += sh[i];
        asm volatile("st.global.cg.f32 [%0], %1;"
                     :: "l"(&g_partials[blockIdx.x]), "f"(p) : "memory");
        unsigned int prev;
        asm volatile("atom.add.release.gpu.u32 %0, [%1], 1;"
                     : "=r"(prev) : "l"(&g_count) : "memory");
        s_last = (prev == (unsigned int)(NBLOCKS - 1));
    }
    __syncthreads();

    if (!s_last) return;

    // Consumer side: ONE acquire fence for the whole kernel, then fixed-order
    // L2 reads (deterministic across replays).
    asm volatile("fence.acq_rel.gpu;" ::: "memory");
    {
        const int tid = threadIdx.x;
        const float4* pp = reinterpret_cast<const float4*>(g_partials);
        float acc = 0.0f;
#pragma unroll
        for (int i = 0; i < NBLOCKS / (THREADS * 4); ++i) {
            const float4 w = __ldcg(&pp[tid + i * THREADS]);
            acc += (w.x + w.y) + (w.z + w.w);
        }
#pragma unroll
        for (int off = 16; off > 0; off >>= 1)
            acc += __shfl_xor_sync(0xFFFFFFFFu, acc, off);

        __shared__ float shw[ROWS_PER_BLOCK];
        if (lane == 0) shw[warp] = acc;
        __syncthreads();
        if (threadIdx.x == 0) {
            float total = 0.0f;
#pragma unroll
            for (int i = 0; i < ROWS_PER_BLOCK; ++i) total += shw[i];
            out[0] = total * (1.0f / (float)B_ROWS);
            g_count = 0; // reset for next graph replay (kernel boundary orders it)
        }
    }
}

extern "C" void kernel_launch(void* const* d_in, const int* in_sizes, int n_in,
                              void* d_out, int out_size) {
    const float* outputs = (const float*)d_in[0];
    const int*   targets = (const int*)d_in[1];
    const int*   ages    = (const int*)d_in[2];
    const float* weight  = (const float*)d_in[3];
    float*       out     = (float*)d_out;

    loss_fused_kernel<<<NBLOCKS, THREADS>>>(outputs, targets, ages, weight, out);
}

// round 9
// speedup vs baseline: 1.0849x; 1.0743x over previous
#include <cuda_runtime.h>
#include <math_constants.h>

// Problem constants (fixed by the reference):
//   outputs: (B, C) fp32, targets: (B,) i32, ages: (B,) i32, weight: (C,) fp32
//   T = 2.0 softmax temperature; output = scalar fp32 mean loss.
//
// Evidence (R1-R8): best stage-1 = float4 two-pass, 256thr/8rows (~22.8us);
// every in-kernel fused reduction costs ~5us regardless of sync mechanism.
// The 4.35us second-kernel cost is launch latency, not work -> hide it with
// programmatic dependent launch (PDL): the reduce kernel launches early and
// spins in griddepcontrol.wait overlapped with stage-1 execution.
#define B_ROWS 32768
#define C_COLS 1024
#define ROWS_PER_BLOCK 8
#define THREADS (ROWS_PER_BLOCK * 32)
#define NBLOCKS (B_ROWS / ROWS_PER_BLOCK) // 4096

// Scratch for deterministic two-stage reduction (no cudaMalloc allowed).
__device__ float g_partials[NBLOCKS];

// Stage 1: one warp per row. Row (1024 fp32 = 4 KB) register-resident; the
// two-pass max->exp structure keeps all values live so ptxas front-batches
// all 8 LDG.128 (this shape measured fastest across R1-R8).
__global__ __launch_bounds__(THREADS)
void loss_rows_kernel(const float* __restrict__ outputs,
                      const int*   __restrict__ targets,
                      const int*   __restrict__ ages,
                      const float* __restrict__ weight) {
    const int warp = threadIdx.x >> 5;
    const int lane = threadIdx.x & 31;
    const int row  = blockIdx.x * ROWS_PER_BLOCK + warp;

    const float4* rp = reinterpret_cast<const float4*>(
        outputs + (size_t)row * C_COLS);

    float4 v[8];
#pragma unroll
    for (int k = 0; k < 8; ++k) v[k] = __ldcs(&rp[k * 32 + lane]);

    // Pass 1: scale by 1/T and per-lane max (4 parallel max chains).
    float m0 = -CUDART_INF_F, m1 = -CUDART_INF_F;
    float m2 = -CUDART_INF_F, m3 = -CUDART_INF_F;
#pragma unroll
    for (int k = 0; k < 8; ++k) {
        v[k].x *= 0.5f; v[k].y *= 0.5f; v[k].z *= 0.5f; v[k].w *= 0.5f;
        m0 = fmaxf(m0, v[k].x); m1 = fmaxf(m1, v[k].y);
        m2 = fmaxf(m2, v[k].z); m3 = fmaxf(m3, v[k].w);
    }
    float m = fmaxf(fmaxf(m0, m1), fmaxf(m2, m3));
#pragma unroll
    for (int off = 16; off > 0; off >>= 1)
        m = fmaxf(m, __shfl_xor_sync(0xFFFFFFFFu, m, off));

    // Pass 2: exp-sum with 4 parallel accumulators.
    float s0 = 0.0f, s1 = 0.0f, s2 = 0.0f, s3 = 0.0f;
#pragma unroll
    for (int k = 0; k < 8; ++k) {
        s0 += __expf(v[k].x - m);
        s1 += __expf(v[k].y - m);
        s2 += __expf(v[k].z - m);
        s3 += __expf(v[k].w - m);
    }
    float s = (s0 + s1) + (s2 + s3);
#pragma unroll
    for (int off = 16; off > 0; off >>= 1)
        s += __shfl_xor_sync(0xFFFFFFFFu, s, off);

    __shared__ float sh[ROWS_PER_BLOCK];
    if (lane == 0) {
        const float lse = m + __logf(s);
        const int   t    = targets[row];
        const float agef = (float)ages[row];
        const float delta = (agef > 50.0f && agef < 60.0f)
                                ? (agef - 50.0f) * 0.1f : 0.0f;
        // Re-reads of this row hit L1 (lines just streamed by this warp).
        const float yt  = outputs[(size_t)row * C_COLS + t]     * 0.5f;
        const float yt1 = outputs[(size_t)row * C_COLS + t + 1] * 0.5f;
        const float loss = -((1.0f - delta) * weight[t]     * (yt  - lse)
                           +         delta  * weight[t + 1] * (yt1 - lse));
        sh[warp] = loss;
    }
    __syncthreads();
    if (threadIdx.x == 0) {
        float p = 0.0f;
#pragma unroll
        for (int i = 0; i < ROWS_PER_BLOCK; ++i) p += sh[i];
        // Straight to L2 so the dependent grid's reads see it.
        asm volatile("st.global.cg.f32 [%0], %1;"
                     :: "l"(&g_partials[blockIdx.x]), "f"(p) : "memory");
    }
    __syncthreads();
    // Signal PDL: once every CTA has executed this (or exited), the
    // dependent reduce grid may proceed past griddepcontrol.wait.
    asm volatile("griddepcontrol.launch_dependents;" ::: "memory");
}

// Stage 2: launched with programmatic stream serialization; its launch ramp
// overlaps stage 1. Deterministic fixed-order reduce of 4096 partials.
__global__ __launch_bounds__(1024)
void reduce_kernel(float* __restrict__ out) {
    // Wait for the primary grid (acquire-paired with launch_dependents).
    asm volatile("griddepcontrol.wait;" ::: "memory");

    const int tid  = threadIdx.x;
    const int lane = tid & 31;
    const int warp = tid >> 5;

    const float4* pp = reinterpret_cast<const float4*>(g_partials);
    const float4 v = __ldcg(&pp[tid]);
    float s = (v.x + v.y) + (v.z + v.w);

#pragma unroll
    for (int off = 16; off > 0; off >>= 1)
        s += __shfl_xor_sync(0xFFFFFFFFu, s, off);

    __shared__ float sh[32];
    if (lane == 0) sh[warp] = s;
    __syncthreads();
    if (warp == 0) {
        float t = sh[lane];
#pragma unroll
        for (int off = 16; off > 0; off >>= 1)
            t += __shfl_xor_sync(0xFFFFFFFFu, t, off);
        if (lane == 0) out[0] = t * (1.0f / (float)B_ROWS);
    }
}

extern "C" void kernel_launch(void* const* d_in, const int* in_sizes, int n_in,
                              void* d_out, int out_size) {
    const float* outputs = (const float*)d_in[0];
    const int*   targets = (const int*)d_in[1];
    const int*   ages    = (const int*)d_in[2];
    const float* weight  = (const float*)d_in[3];
    float*       out     = (float*)d_out;

    loss_rows_kernel<<<NBLOCKS, THREADS>>>(outputs, targets, ages, weight);

    // Reduce kernel with programmatic dependent launch: launches while
    // stage 1 runs; griddepcontrol.wait provides the ordering.
    cudaLaunchConfig_t cfg = {};
    cfg.gridDim  = dim3(1, 1, 1);
    cfg.blockDim = dim3(1024, 1, 1);
    cfg.dynamicSmemBytes = 0;
    cfg.stream = 0; // legacy default stream (same as <<<>>> above)
    cudaLaunchAttribute attr[1];
    attr[0].id = cudaLaunchAttributeProgrammaticStreamSerialization;
    attr[0].val.programmaticStreamSerializationAllowed = 1;
    cfg.attrs = attr;
    cfg.numAttrs = 1;
    cudaLaunchKernelEx(&cfg, reduce_kernel, out);
}